// round 12
// baseline (speedup 1.0000x reference)
#include <cuda_runtime.h>
#include <cuda_bf16.h>
#include <cstdint>

// ---------------------------------------------------------------------------
// Problem constants
// ---------------------------------------------------------------------------
#define EMBED   256
#define NHEADS  8
#define BATCH   4
#define NQ      5440
#define NV      5440
#define MROWS   (BATCH * NQ)   // 21760 = 170 * 128
#define KSPLIT  512            // [hi(256) | lo(256)] bf16

// ---------------------------------------------------------------------------
// Scratch (device globals; no allocation allowed)
// ---------------------------------------------------------------------------
#define VPAD    (66 * EMBED)
__device__ float g_vbuf[(size_t)VPAD + (size_t)MROWS * EMBED + (size_t)VPAD];
__device__ float g_off[(size_t)MROWS * EMBED];
__device__ float g_aw [(size_t)MROWS * 128];

__device__ __nv_bfloat16 g_Av [(size_t)MROWS * KSPLIT];  // value  split
__device__ __nv_bfloat16 g_Aq [(size_t)MROWS * KSPLIT];  // query  split
__device__ __nv_bfloat16 g_Aat[(size_t)MROWS * KSPLIT];  // attn-out split (from msda)
__device__ __nv_bfloat16 g_Bv  [256 * KSPLIT];           // weights split (K-major)
__device__ __nv_bfloat16 g_Bo  [256 * KSPLIT];
__device__ __nv_bfloat16 g_Ba  [128 * KSPLIT];
__device__ __nv_bfloat16 g_Bout[256 * KSPLIT];

// ---------------------------------------------------------------------------
// PTX helpers (baseline compute_103-safe)
// ---------------------------------------------------------------------------
__device__ __forceinline__ uint32_t smem_u32(const void* p) {
    uint32_t a;
    asm("{ .reg .u64 t; cvta.to.shared.u64 t, %1; cvt.u32.u64 %0, t; }"
        : "=r"(a) : "l"(p));
    return a;
}
__device__ __forceinline__ void cp_async16(uint32_t dst, const void* src) {
    asm volatile("cp.async.cg.shared.global [%0], [%1], 16;"
                 :: "r"(dst), "l"(src) : "memory");
}
__device__ __forceinline__ void cp_commit() {
    asm volatile("cp.async.commit_group;" ::: "memory");
}
template <int N>
__device__ __forceinline__ void cp_wait() {
    asm volatile("cp.async.wait_group %0;" :: "n"(N) : "memory");
}
__device__ __forceinline__ void ldsm_x4(uint32_t& r0, uint32_t& r1,
                                        uint32_t& r2, uint32_t& r3, uint32_t a) {
    asm volatile("ldmatrix.sync.aligned.m8n8.x4.shared.b16 {%0,%1,%2,%3}, [%4];"
                 : "=r"(r0), "=r"(r1), "=r"(r2), "=r"(r3) : "r"(a));
}
__device__ __forceinline__ void mma16816(float* d, const uint32_t* a,
                                         uint32_t b0, uint32_t b1) {
    asm volatile(
        "mma.sync.aligned.m16n8k16.row.col.f32.bf16.bf16.f32 "
        "{%0,%1,%2,%3}, {%4,%5,%6,%7}, {%8,%9}, {%0,%1,%2,%3};"
        : "+f"(d[0]), "+f"(d[1]), "+f"(d[2]), "+f"(d[3])
        : "r"(a[0]), "r"(a[1]), "r"(a[2]), "r"(a[3]), "r"(b0), "r"(b1));
}

// ---------------------------------------------------------------------------
// Fused fp32 -> split-bf16 conversion (activations + all 4 weight matrices)
// ---------------------------------------------------------------------------
__device__ __forceinline__ void conv_act_body(
    const float* __restrict__ in, __nv_bfloat16* __restrict__ out, int i)
{
    int r = i >> 6, k4 = (i & 63) << 2;
    float4 x = *(const float4*)(in + (size_t)r * 256 + k4);
    alignas(8) __nv_bfloat16 h[4], l[4];
    h[0] = __float2bfloat16(x.x); l[0] = __float2bfloat16(x.x - __bfloat162float(h[0]));
    h[1] = __float2bfloat16(x.y); l[1] = __float2bfloat16(x.y - __bfloat162float(h[1]));
    h[2] = __float2bfloat16(x.z); l[2] = __float2bfloat16(x.z - __bfloat162float(h[2]));
    h[3] = __float2bfloat16(x.w); l[3] = __float2bfloat16(x.w - __bfloat162float(h[3]));
    *(uint2*)(out + (size_t)r * KSPLIT + k4)       = *(uint2*)h;
    *(uint2*)(out + (size_t)r * KSPLIT + 256 + k4) = *(uint2*)l;
}
__device__ __forceinline__ void conv_wt_body(
    const float* __restrict__ W, __nv_bfloat16* __restrict__ out, int N, int i)
{
    int n = i >> 8, k = i & 255;
    float x = W[(size_t)k * N + n];
    __nv_bfloat16 h = __float2bfloat16(x);
    out[(size_t)n * KSPLIT + k]       = h;
    out[(size_t)n * KSPLIT + 256 + k] = __float2bfloat16(x - __bfloat162float(h));
}

// grid segments: [0,5440) value, [5440,10880) query,
// [10880,11136) Wv, [11136,11392) Wo, [11392,11520) Wa, [11520,11776) Wout
__global__ __launch_bounds__(256) void conv_all(
    const float* __restrict__ value, const float* __restrict__ query,
    const float* __restrict__ Wv, const float* __restrict__ Wo,
    const float* __restrict__ Wa, const float* __restrict__ Wout,
    __nv_bfloat16* __restrict__ Av, __nv_bfloat16* __restrict__ Aq,
    __nv_bfloat16* __restrict__ Bv, __nv_bfloat16* __restrict__ Bo,
    __nv_bfloat16* __restrict__ Ba, __nv_bfloat16* __restrict__ Bout)
{
    const int id = blockIdx.x, tid = threadIdx.x;
    if (id < 5440) {
        conv_act_body(value, Av, id * 256 + tid);
    } else if (id < 10880) {
        conv_act_body(query, Aq, (id - 5440) * 256 + tid);
    } else if (id < 11136) {
        conv_wt_body(Wv, Bv, 256, (id - 10880) * 256 + tid);
    } else if (id < 11392) {
        conv_wt_body(Wo, Bo, 256, (id - 11136) * 256 + tid);
    } else if (id < 11520) {
        conv_wt_body(Wa, Ba, 128, (id - 11392) * 256 + tid);
    } else {
        conv_wt_body(Wout, Bout, 256, (id - 11520) * 256 + tid);
    }
}

// ---------------------------------------------------------------------------
// HMMA GEMM body v4: CTA tile 128x128, 8 warps @ 64x32, fused 3-term passes.
// 8 super-chunks of 32 K-cols. Each smem row packs [hi 64B | lo 64B], so per
// ks we ldsm af_hi,bf_hi,bf_lo once, run mma(hi*hi) + mma(hi*lo), then
// overwrite-ldsm af_lo for mma(lo*hi). ldsm count per tile drops 288 -> 192
// (CTA smem reads 1152KB -> 768KB) with identical HMMA work and math terms.
// 3-stage cp.async ring, one __syncthreads per super-chunk.
// ---------------------------------------------------------------------------
#define NSUPER 8
#define STG    32768                 // A(16K) + B(16K): 128 rows x 128B each
#define GSMEM  (3 * STG)             // 96 KB

__device__ __forceinline__ void gemm_body(
    const __nv_bfloat16* __restrict__ A, const __nv_bfloat16* __restrict__ B,
    const float* __restrict__ bias, float* __restrict__ C, int N,
    int r0, int c0, char* smem)
{
    const uint32_t sb = smem_u32(smem);
    const int tid = threadIdx.x, wid = tid >> 5, lane = tid & 31;
    const int warp_m = wid & 1, warp_n = wid >> 1;   // 2 x 4 warp grid

    const int cpRow  = tid >> 1;          // 0..127
    const int cpHalf = tid & 1;           // 0: hi (units 0-3), 1: lo (units 4-7)

    // super-chunk s covers K-cols [s*32, s*32+32) of the hi range; lo at +256.
    auto prefetch = [&](int s, int st) {
        const int kcol = cpHalf * 256 + s * 32;      // element offset in row
        const __nv_bfloat16* ga = A + (size_t)(r0 + cpRow) * KSPLIT + kcol;
        const __nv_bfloat16* gb = B + (size_t)(c0 + cpRow) * KSPLIT + kcol;
        const uint32_t sa = sb + st * STG + cpRow * 128;
        const uint32_t sg = sa + 16384;
        const int swz = cpRow & 7;
#pragma unroll
        for (int i = 0; i < 4; i++) {
            const int u = cpHalf * 4 + i;            // unit 0-7 within 128B row
            cp_async16(sa + ((u ^ swz) << 4), ga + i * 8);
            cp_async16(sg + ((u ^ swz) << 4), gb + i * 8);
        }
        cp_commit();
    };

    const int r7   = lane & 7;
    const int arow = (lane & 7) | (((lane >> 3) & 1) << 3);
    const int ah   = (lane >> 4) & 1;
    const int brow = (lane & 7) | (((lane >> 4) & 1) << 3);
    const int bh   = (lane >> 3) & 1;

    float acc[4][4][4];
#pragma unroll
    for (int mi = 0; mi < 4; mi++)
#pragma unroll
        for (int ni = 0; ni < 4; ni++)
#pragma unroll
            for (int j = 0; j < 4; j++) acc[mi][ni][j] = 0.f;

    prefetch(0, 0);
    prefetch(1, 1);

    for (int s = 0; s < NSUPER; s++) {
        if (s + 1 < NSUPER) cp_wait<1>(); else cp_wait<0>();
        __syncthreads();
        if (s + 2 < NSUPER) prefetch(s + 2, (s + 2) % 3);

        const uint32_t Ast = sb + (s % 3) * STG;
        const uint32_t Bst = Ast + 16384;

#pragma unroll
        for (int ks = 0; ks < 2; ks++) {
            uint32_t af[4][4];
            // af_hi: units 0-3
#pragma unroll
            for (int mi = 0; mi < 4; mi++) {
                const int row = warp_m * 64 + mi * 16 + arow;
                const uint32_t addr = Ast + row * 128 + (((ks * 2 + ah) ^ r7) << 4);
                ldsm_x4(af[mi][0], af[mi][1], af[mi][2], af[mi][3], addr);
            }
            uint32_t bfh[4][2], bfl[4][2];
#pragma unroll
            for (int nh = 0; nh < 2; nh++) {
                const int row = warp_n * 32 + nh * 16 + brow;
                uint32_t t0, t1, t2, t3;
                // bf_hi: units 0-3
                ldsm_x4(t0, t1, t2, t3,
                        Bst + row * 128 + (((ks * 2 + bh) ^ r7) << 4));
                bfh[nh * 2][0] = t0; bfh[nh * 2][1] = t1;
                bfh[nh * 2 + 1][0] = t2; bfh[nh * 2 + 1][1] = t3;
                // bf_lo: units 4-7
                ldsm_x4(t0, t1, t2, t3,
                        Bst + row * 128 + (((4 + ks * 2 + bh) ^ r7) << 4));
                bfl[nh * 2][0] = t0; bfl[nh * 2][1] = t1;
                bfl[nh * 2 + 1][0] = t2; bfl[nh * 2 + 1][1] = t3;
            }
            // hi * hi
#pragma unroll
            for (int mi = 0; mi < 4; mi++)
#pragma unroll
                for (int ni = 0; ni < 4; ni++)
                    mma16816(acc[mi][ni], af[mi], bfh[ni][0], bfh[ni][1]);
            // hi * lo
#pragma unroll
            for (int mi = 0; mi < 4; mi++)
#pragma unroll
                for (int ni = 0; ni < 4; ni++)
                    mma16816(acc[mi][ni], af[mi], bfl[ni][0], bfl[ni][1]);
            // af_lo: units 4-7 (overwrite af)
#pragma unroll
            for (int mi = 0; mi < 4; mi++) {
                const int row = warp_m * 64 + mi * 16 + arow;
                const uint32_t addr = Ast + row * 128 + (((4 + ks * 2 + ah) ^ r7) << 4);
                ldsm_x4(af[mi][0], af[mi][1], af[mi][2], af[mi][3], addr);
            }
            // lo * hi
#pragma unroll
            for (int mi = 0; mi < 4; mi++)
#pragma unroll
                for (int ni = 0; ni < 4; ni++)
                    mma16816(acc[mi][ni], af[mi], bfh[ni][0], bfh[ni][1]);
        }
    }

    // epilogue: bias + store
    const int g = lane >> 2, tig = lane & 3;
    float2 bb[4];
#pragma unroll
    for (int ni = 0; ni < 4; ni++)
        bb[ni] = *(const float2*)(bias + c0 + warp_n * 32 + ni * 8 + tig * 2);
#pragma unroll
    for (int mi = 0; mi < 4; mi++) {
        const int rowg = r0 + warp_m * 64 + mi * 16 + g;
        float* p0 = C + (size_t)rowg * N + c0 + warp_n * 32 + tig * 2;
        float* p1 = p0 + (size_t)8 * N;
#pragma unroll
        for (int ni = 0; ni < 4; ni++) {
            float2 o0 = { acc[mi][ni][0] + bb[ni].x, acc[mi][ni][1] + bb[ni].y };
            float2 o1 = { acc[mi][ni][2] + bb[ni].x, acc[mi][ni][3] + bb[ni].y };
            *(float2*)(p0 + ni * 8) = o0;
            *(float2*)(p1 + ni * 8) = o1;
        }
    }
}

// Fused: seg0 value-proj (340 CTAs), seg1 offsets (340), seg2 logits (170)
__global__ __launch_bounds__(256, 2) void gemm_fused3(
    const __nv_bfloat16* __restrict__ Av, const __nv_bfloat16* __restrict__ Aq,
    const __nv_bfloat16* __restrict__ Bv, const __nv_bfloat16* __restrict__ Bo,
    const __nv_bfloat16* __restrict__ Ba,
    const float* __restrict__ bv, const float* __restrict__ bo,
    const float* __restrict__ ba,
    float* __restrict__ Cv, float* __restrict__ Co, float* __restrict__ Ca)
{
    extern __shared__ char smem[];
    int id = blockIdx.x;
    if (id < 340) {
        gemm_body(Av, Bv, bv, Cv, 256, (id >> 1) * 128, (id & 1) * 128, smem);
    } else if (id < 680) {
        id -= 340;
        gemm_body(Aq, Bo, bo, Co, 256, (id >> 1) * 128, (id & 1) * 128, smem);
    } else {
        id -= 680;
        gemm_body(Aq, Ba, ba, Ca, 128, id * 128, 0, smem);
    }
}

__global__ __launch_bounds__(256, 2) void gemm_out(
    const __nv_bfloat16* __restrict__ A, const __nv_bfloat16* __restrict__ B,
    const float* __restrict__ bias, float* __restrict__ C)
{
    extern __shared__ char smem[];
    gemm_body(A, B, bias, C, 256, (blockIdx.x >> 1) * 128, (blockIdx.x & 1) * 128, smem);
}

// ---------------------------------------------------------------------------
// Deformable sampling v3 (unchanged): one warp per (b, q, head).
// ---------------------------------------------------------------------------
__global__ __launch_bounds__(256) void msda_sample(
    const float* __restrict__ v, const float* __restrict__ off,
    const float* __restrict__ aw, const float* __restrict__ ref,
    __nv_bfloat16* __restrict__ outs)   // (B*NQ, 512) = [hi|lo]
{
    const int bq   = blockIdx.x;
    const int head = threadIdx.x >> 5;
    const int lane = threadIdx.x & 31;
    const int b    = bq / NQ;
    const unsigned FULL = 0xffffffffu;

    // ---- softmax over 16 logits ----
    const float* awp = aw + ((size_t)bq * NHEADS + head) * 16;
    const float NEG_INF = __int_as_float(0xff800000u);
    float a = (lane < 16) ? awp[lane] : NEG_INF;
    float m = a;
#pragma unroll
    for (int o = 16; o; o >>= 1) m = fmaxf(m, __shfl_xor_sync(FULL, m, o));
    float e = (lane < 16) ? expf(a - m) : 0.f;
    float s = e;
#pragma unroll
    for (int o = 16; o; o >>= 1) s += __shfl_xor_sync(FULL, s, o);
    const float p = e / s;

    // ---- phase 1: lane j (<16) computes point j's base offset + weights ----
    const float offv = off[(size_t)bq * EMBED + head * 32 + lane];
    const float ox = __shfl_sync(FULL, offv, 2 * lane);
    const float oy = __shfl_sync(FULL, offv, 2 * lane + 1);
    const float refv = (lane < 8) ? ref[(size_t)bq * 8 + lane] : 0.f;
    const int   l  = (lane >> 2) & 3;
    const float rx = __shfl_sync(FULL, refv, 2 * l);
    const float ry = __shfl_sync(FULL, refv, 2 * l + 1);

    const int   Wi  = 64 >> l;
    const float Wf  = (float)Wi;
    const int   cur = (16384 - (16384 >> (2 * l))) / 3;

    const float px = (rx + ox / Wf) * Wf - 0.5f;
    const float py = (ry + oy / Wf) * Wf - 0.5f;
    const float x0f = floorf(px), y0f = floorf(py);
    const float wx = px - x0f,    wy = py - y0f;
    const int x0 = (int)x0f, y0 = (int)y0f;

    const bool vx0 = (x0 >= 0)  & (x0 < Wi);
    const bool vx1 = (x0 >= -1) & (x0 < Wi - 1);
    const bool vy0 = (y0 >= 0)  & (y0 < Wi);
    const bool vy1 = (y0 >= -1) & (y0 < Wi - 1);
    const float u = 1.f - wx, t = 1.f - wy;

    float c00 = (vx0 && vy0) ? p * u  * t  : 0.f;
    float c10 = (vx1 && vy0) ? p * wx * t  : 0.f;
    float c01 = (vx0 && vy1) ? p * u  * wy : 0.f;
    float c11 = (vx1 && vy1) ? p * wx * wy : 0.f;

    int idx = cur + y0 * Wi + x0;
    idx = min(max(idx, -65), NV - 1);
    const int o00 = idx << 10;

    // ---- phase 2: 4 iterations, 4 parallel points, float4 channels ----
    const int pg = lane >> 3;           // point slot 0..3
    const int c4 = lane & 7;            // channel quad 0..7
    const char* vb = (const char*)(v + (size_t)b * NV * EMBED + head * 32 + c4 * 4);

    float a0 = 0.f, a1 = 0.f, a2 = 0.f, a3 = 0.f;
#pragma unroll
    for (int it = 0; it < 4; it++) {
        const int rowB = (64 >> it) << 10;        // level == it
        const int src = it * 4 + pg;              // point index
        const int   io  = __shfl_sync(FULL, o00, src);
        const float w00 = __shfl_sync(FULL, c00, src);
        const float w10 = __shfl_sync(FULL, c10, src);
        const float w01 = __shfl_sync(FULL, c01, src);
        const float w11 = __shfl_sync(FULL, c11, src);
        const char* ad = vb + io;
        const float4 v00 = *(const float4*)(ad);
        const float4 v10 = *(const float4*)(ad + 1024);
        const float4 v01 = *(const float4*)(ad + rowB);
        const float4 v11 = *(const float4*)(ad + rowB + 1024);
        a0 = fmaf(w00, v00.x, a0); a1 = fmaf(w00, v00.y, a1);
        a2 = fmaf(w00, v00.z, a2); a3 = fmaf(w00, v00.w, a3);
        a0 = fmaf(w10, v10.x, a0); a1 = fmaf(w10, v10.y, a1);
        a2 = fmaf(w10, v10.z, a2); a3 = fmaf(w10, v10.w, a3);
        a0 = fmaf(w01, v01.x, a0); a1 = fmaf(w01, v01.y, a1);
        a2 = fmaf(w01, v01.z, a2); a3 = fmaf(w01, v01.w, a3);
        a0 = fmaf(w11, v11.x, a0); a1 = fmaf(w11, v11.y, a1);
        a2 = fmaf(w11, v11.z, a2); a3 = fmaf(w11, v11.w, a3);
    }
    // reduce over point slots (lane bits 3,4)
    a0 += __shfl_xor_sync(FULL, a0, 8);  a1 += __shfl_xor_sync(FULL, a1, 8);
    a2 += __shfl_xor_sync(FULL, a2, 8);  a3 += __shfl_xor_sync(FULL, a3, 8);
    a0 += __shfl_xor_sync(FULL, a0, 16); a1 += __shfl_xor_sync(FULL, a1, 16);
    a2 += __shfl_xor_sync(FULL, a2, 16); a3 += __shfl_xor_sync(FULL, a3, 16);

    // ---- epilogue: split-bf16 write (lanes 0-7 only) ----
    if (pg == 0) {
        alignas(8) __nv_bfloat16 h[4], lo[4];
        h[0] = __float2bfloat16(a0); lo[0] = __float2bfloat16(a0 - __bfloat162float(h[0]));
        h[1] = __float2bfloat16(a1); lo[1] = __float2bfloat16(a1 - __bfloat162float(h[1]));
        h[2] = __float2bfloat16(a2); lo[2] = __float2bfloat16(a2 - __bfloat162float(h[2]));
        h[3] = __float2bfloat16(a3); lo[3] = __float2bfloat16(a3 - __bfloat162float(h[3]));
        const size_t base = (size_t)bq * KSPLIT + head * 32 + c4 * 4;
        *(uint2*)(outs + base)       = *(uint2*)h;
        *(uint2*)(outs + base + 256) = *(uint2*)lo;
    }
}

// ---------------------------------------------------------------------------
// Launch (4 launches total)
// ---------------------------------------------------------------------------
extern "C" void kernel_launch(void* const* d_in, const int* in_sizes, int n_in,
                              void* d_out, int out_size)
{
    const float* query = (const float*)d_in[0];
    const float* value = (const float*)d_in[1];
    const float* refp  = (const float*)d_in[2];
    const float* Wv    = (const float*)d_in[3];
    const float* bv    = (const float*)d_in[4];
    const float* Wo    = (const float*)d_in[5];
    const float* bo    = (const float*)d_in[6];
    const float* Wa    = (const float*)d_in[7];
    const float* ba    = (const float*)d_in[8];
    const float* Wout  = (const float*)d_in[9];
    const float* bout  = (const float*)d_in[10];
    float* out = (float*)d_out;

    float *pvraw, *poff, *paw;
    __nv_bfloat16 *pAv, *pAq, *pAat, *pBv, *pBo, *pBa, *pBout;
    cudaGetSymbolAddress((void**)&pvraw, g_vbuf);
    cudaGetSymbolAddress((void**)&poff,  g_off);
    cudaGetSymbolAddress((void**)&paw,   g_aw);
    cudaGetSymbolAddress((void**)&pAv,   g_Av);
    cudaGetSymbolAddress((void**)&pAq,   g_Aq);
    cudaGetSymbolAddress((void**)&pAat,  g_Aat);
    cudaGetSymbolAddress((void**)&pBv,   g_Bv);
    cudaGetSymbolAddress((void**)&pBo,   g_Bo);
    cudaGetSymbolAddress((void**)&pBa,   g_Ba);
    cudaGetSymbolAddress((void**)&pBout, g_Bout);
    float* pv = pvraw + VPAD;

    cudaFuncSetAttribute(gemm_fused3, cudaFuncAttributeMaxDynamicSharedMemorySize, GSMEM);
    cudaFuncSetAttribute(gemm_out,    cudaFuncAttributeMaxDynamicSharedMemorySize, GSMEM);

    conv_all<<<11776, 256>>>(value, query, Wv, Wo, Wa, Wout,
                             pAv, pAq, pBv, pBo, pBa, pBout);

    gemm_fused3<<<850, 256, GSMEM>>>(pAv, pAq, pBv, pBo, pBa,
                                     bv, bo, ba, pv, poff, paw);

    msda_sample<<<MROWS, 256>>>(pv, poff, paw, refp, pAat);

    gemm_out<<<340, 256, GSMEM>>>(pAat, pBout, bout, out);
}

// round 13
// speedup vs baseline: 1.0902x; 1.0902x over previous
#include <cuda_runtime.h>
#include <cuda_bf16.h>
#include <cstdint>

// ---------------------------------------------------------------------------
// Problem constants
// ---------------------------------------------------------------------------
#define EMBED   256
#define NHEADS  8
#define BATCH   4
#define NQ      5440
#define NV      5440
#define MROWS   (BATCH * NQ)   // 21760 = 170 * 128
#define KSPLIT  512            // [hi(256) | lo(256)] bf16

// ---------------------------------------------------------------------------
// Scratch (device globals; no allocation allowed)
// ---------------------------------------------------------------------------
#define VPAD    (66 * EMBED)
__device__ float g_vbuf[(size_t)VPAD + (size_t)MROWS * EMBED + (size_t)VPAD];
__device__ float g_off[(size_t)MROWS * EMBED];
__device__ float g_aw [(size_t)MROWS * 128];

__device__ __nv_bfloat16 g_Av [(size_t)MROWS * KSPLIT];  // value  split
__device__ __nv_bfloat16 g_Aq [(size_t)MROWS * KSPLIT];  // query  split
__device__ __nv_bfloat16 g_Aat[(size_t)MROWS * KSPLIT];  // attn-out split (from msda)
__device__ __nv_bfloat16 g_Bv  [256 * KSPLIT];           // weights split (K-major)
__device__ __nv_bfloat16 g_Bo  [256 * KSPLIT];
__device__ __nv_bfloat16 g_Ba  [128 * KSPLIT];
__device__ __nv_bfloat16 g_Bout[256 * KSPLIT];

// ---------------------------------------------------------------------------
// PTX helpers (baseline compute_103-safe)
// ---------------------------------------------------------------------------
__device__ __forceinline__ uint32_t smem_u32(const void* p) {
    uint32_t a;
    asm("{ .reg .u64 t; cvta.to.shared.u64 t, %1; cvt.u32.u64 %0, t; }"
        : "=r"(a) : "l"(p));
    return a;
}
__device__ __forceinline__ void cp_async16(uint32_t dst, const void* src) {
    asm volatile("cp.async.cg.shared.global [%0], [%1], 16;"
                 :: "r"(dst), "l"(src) : "memory");
}
__device__ __forceinline__ void cp_commit() {
    asm volatile("cp.async.commit_group;" ::: "memory");
}
template <int N>
__device__ __forceinline__ void cp_wait() {
    asm volatile("cp.async.wait_group %0;" :: "n"(N) : "memory");
}
__device__ __forceinline__ void ldsm_x4(uint32_t& r0, uint32_t& r1,
                                        uint32_t& r2, uint32_t& r3, uint32_t a) {
    asm volatile("ldmatrix.sync.aligned.m8n8.x4.shared.b16 {%0,%1,%2,%3}, [%4];"
                 : "=r"(r0), "=r"(r1), "=r"(r2), "=r"(r3) : "r"(a));
}
__device__ __forceinline__ void mma16816(float* d, const uint32_t* a,
                                         uint32_t b0, uint32_t b1) {
    asm volatile(
        "mma.sync.aligned.m16n8k16.row.col.f32.bf16.bf16.f32 "
        "{%0,%1,%2,%3}, {%4,%5,%6,%7}, {%8,%9}, {%0,%1,%2,%3};"
        : "+f"(d[0]), "+f"(d[1]), "+f"(d[2]), "+f"(d[3])
        : "r"(a[0]), "r"(a[1]), "r"(a[2]), "r"(a[3]), "r"(b0), "r"(b1));
}

// ---------------------------------------------------------------------------
// Fused fp32 -> split-bf16 conversion (activations + all 4 weight matrices)
// ---------------------------------------------------------------------------
__device__ __forceinline__ void conv_act_body(
    const float* __restrict__ in, __nv_bfloat16* __restrict__ out, int i)
{
    int r = i >> 6, k4 = (i & 63) << 2;
    float4 x = *(const float4*)(in + (size_t)r * 256 + k4);
    alignas(8) __nv_bfloat16 h[4], l[4];
    h[0] = __float2bfloat16(x.x); l[0] = __float2bfloat16(x.x - __bfloat162float(h[0]));
    h[1] = __float2bfloat16(x.y); l[1] = __float2bfloat16(x.y - __bfloat162float(h[1]));
    h[2] = __float2bfloat16(x.z); l[2] = __float2bfloat16(x.z - __bfloat162float(h[2]));
    h[3] = __float2bfloat16(x.w); l[3] = __float2bfloat16(x.w - __bfloat162float(h[3]));
    *(uint2*)(out + (size_t)r * KSPLIT + k4)       = *(uint2*)h;
    *(uint2*)(out + (size_t)r * KSPLIT + 256 + k4) = *(uint2*)l;
}
__device__ __forceinline__ void conv_wt_body(
    const float* __restrict__ W, __nv_bfloat16* __restrict__ out, int N, int i)
{
    int n = i >> 8, k = i & 255;
    float x = W[(size_t)k * N + n];
    __nv_bfloat16 h = __float2bfloat16(x);
    out[(size_t)n * KSPLIT + k]       = h;
    out[(size_t)n * KSPLIT + 256 + k] = __float2bfloat16(x - __bfloat162float(h));
}

// grid segments: [0,5440) value, [5440,10880) query,
// [10880,11136) Wv, [11136,11392) Wo, [11392,11520) Wa, [11520,11776) Wout
__global__ __launch_bounds__(256) void conv_all(
    const float* __restrict__ value, const float* __restrict__ query,
    const float* __restrict__ Wv, const float* __restrict__ Wo,
    const float* __restrict__ Wa, const float* __restrict__ Wout,
    __nv_bfloat16* __restrict__ Av, __nv_bfloat16* __restrict__ Aq,
    __nv_bfloat16* __restrict__ Bv, __nv_bfloat16* __restrict__ Bo,
    __nv_bfloat16* __restrict__ Ba, __nv_bfloat16* __restrict__ Bout)
{
    const int id = blockIdx.x, tid = threadIdx.x;
    if (id < 5440) {
        conv_act_body(value, Av, id * 256 + tid);
    } else if (id < 10880) {
        conv_act_body(query, Aq, (id - 5440) * 256 + tid);
    } else if (id < 11136) {
        conv_wt_body(Wv, Bv, 256, (id - 10880) * 256 + tid);
    } else if (id < 11392) {
        conv_wt_body(Wo, Bo, 256, (id - 11136) * 256 + tid);
    } else if (id < 11520) {
        conv_wt_body(Wa, Ba, 128, (id - 11392) * 256 + tid);
    } else {
        conv_wt_body(Wout, Bout, 256, (id - 11520) * 256 + tid);
    }
}

// ---------------------------------------------------------------------------
// HMMA GEMM body (R11 proven config): CTA tile 128x128, 8 warps @ 64x32,
// 12 K-chunks of 64, 3-stage cp.async ring, one __syncthreads per chunk.
// ---------------------------------------------------------------------------
#define NCHUNK 12
#define STG    32768                 // A(16K) + B(16K) per stage
#define GSMEM  (3 * STG)             // 96 KB

__device__ __forceinline__ void gemm_body(
    const __nv_bfloat16* __restrict__ A, const __nv_bfloat16* __restrict__ B,
    const float* __restrict__ bias, float* __restrict__ C, int N,
    int r0, int c0, char* smem)
{
    const uint32_t sb = smem_u32(smem);
    const int tid = threadIdx.x, wid = tid >> 5, lane = tid & 31;
    const int warp_m = wid & 1, warp_n = wid >> 1;   // 2 x 4 warp grid

    const int cpRow = tid >> 1;          // 0..127
    const int cpU0  = (tid & 1) * 4;     // 0 or 4 (16B units)

    auto prefetch = [&](int c, int st) {
        const int p  = c >> 2, kc = c & 3;
        const int ka = ((p == 1) ? 256 : 0) + kc * 64;
        const int kb = ((p == 2) ? 256 : 0) + kc * 64;
        const __nv_bfloat16* ga = A + (size_t)(r0 + cpRow) * KSPLIT + ka + cpU0 * 8;
        const __nv_bfloat16* gb = B + (size_t)(c0 + cpRow) * KSPLIT + kb + cpU0 * 8;
        const uint32_t sa = sb + st * STG + cpRow * 128;
        const uint32_t sg = sa + 16384;
        const int swz = cpRow & 7;
#pragma unroll
        for (int i = 0; i < 4; i++) {
            const int u = cpU0 + i;
            cp_async16(sa + ((u ^ swz) << 4), ga + i * 8);
            cp_async16(sg + ((u ^ swz) << 4), gb + i * 8);
        }
        cp_commit();
    };

    const int r7   = lane & 7;
    const int arow = (lane & 7) | (((lane >> 3) & 1) << 3);
    const int ah   = (lane >> 4) & 1;
    const int brow = (lane & 7) | (((lane >> 4) & 1) << 3);
    const int bh   = (lane >> 3) & 1;

    float acc[4][4][4];
#pragma unroll
    for (int mi = 0; mi < 4; mi++)
#pragma unroll
        for (int ni = 0; ni < 4; ni++)
#pragma unroll
            for (int j = 0; j < 4; j++) acc[mi][ni][j] = 0.f;

    prefetch(0, 0);
    prefetch(1, 1);

    for (int c = 0; c < NCHUNK; c++) {
        if (c + 1 < NCHUNK) cp_wait<1>(); else cp_wait<0>();
        __syncthreads();
        if (c + 2 < NCHUNK) prefetch(c + 2, (c + 2) % 3);

        const uint32_t Ast = sb + (c % 3) * STG;
        const uint32_t Bst = Ast + 16384;

#pragma unroll
        for (int ks = 0; ks < 4; ks++) {
            uint32_t af[4][4];
#pragma unroll
            for (int mi = 0; mi < 4; mi++) {
                const int row = warp_m * 64 + mi * 16 + arow;
                const uint32_t addr = Ast + row * 128 + (((ks * 2 + ah) ^ r7) << 4);
                ldsm_x4(af[mi][0], af[mi][1], af[mi][2], af[mi][3], addr);
            }
            uint32_t bf[4][2];
#pragma unroll
            for (int nh = 0; nh < 2; nh++) {
                const int row = warp_n * 32 + nh * 16 + brow;
                const uint32_t addr = Bst + row * 128 + (((ks * 2 + bh) ^ r7) << 4);
                uint32_t t0, t1, t2, t3;
                ldsm_x4(t0, t1, t2, t3, addr);
                bf[nh * 2][0] = t0; bf[nh * 2][1] = t1;
                bf[nh * 2 + 1][0] = t2; bf[nh * 2 + 1][1] = t3;
            }
#pragma unroll
            for (int mi = 0; mi < 4; mi++)
#pragma unroll
                for (int ni = 0; ni < 4; ni++)
                    mma16816(acc[mi][ni], af[mi], bf[ni][0], bf[ni][1]);
        }
    }

    // epilogue: bias + store
    const int g = lane >> 2, tig = lane & 3;
    float2 bb[4];
#pragma unroll
    for (int ni = 0; ni < 4; ni++)
        bb[ni] = *(const float2*)(bias + c0 + warp_n * 32 + ni * 8 + tig * 2);
#pragma unroll
    for (int mi = 0; mi < 4; mi++) {
        const int rowg = r0 + warp_m * 64 + mi * 16 + g;
        float* p0 = C + (size_t)rowg * N + c0 + warp_n * 32 + tig * 2;
        float* p1 = p0 + (size_t)8 * N;
#pragma unroll
        for (int ni = 0; ni < 4; ni++) {
            float2 o0 = { acc[mi][ni][0] + bb[ni].x, acc[mi][ni][1] + bb[ni].y };
            float2 o1 = { acc[mi][ni][2] + bb[ni].x, acc[mi][ni][3] + bb[ni].y };
            *(float2*)(p0 + ni * 8) = o0;
            *(float2*)(p1 + ni * 8) = o1;
        }
    }
}

// Fused: seg0 value-proj (340 CTAs), seg1 offsets (340), seg2 logits (170)
__global__ __launch_bounds__(256, 2) void gemm_fused3(
    const __nv_bfloat16* __restrict__ Av, const __nv_bfloat16* __restrict__ Aq,
    const __nv_bfloat16* __restrict__ Bv, const __nv_bfloat16* __restrict__ Bo,
    const __nv_bfloat16* __restrict__ Ba,
    const float* __restrict__ bv, const float* __restrict__ bo,
    const float* __restrict__ ba,
    float* __restrict__ Cv, float* __restrict__ Co, float* __restrict__ Ca)
{
    extern __shared__ char smem[];
    int id = blockIdx.x;
    if (id < 340) {
        gemm_body(Av, Bv, bv, Cv, 256, (id >> 1) * 128, (id & 1) * 128, smem);
    } else if (id < 680) {
        id -= 340;
        gemm_body(Aq, Bo, bo, Co, 256, (id >> 1) * 128, (id & 1) * 128, smem);
    } else {
        id -= 680;
        gemm_body(Aq, Ba, ba, Ca, 128, id * 128, 0, smem);
    }
}

__global__ __launch_bounds__(256, 2) void gemm_out(
    const __nv_bfloat16* __restrict__ A, const __nv_bfloat16* __restrict__ B,
    const float* __restrict__ bias, float* __restrict__ C)
{
    extern __shared__ char smem[];
    gemm_body(A, B, bias, C, 256, (blockIdx.x >> 1) * 128, (blockIdx.x & 1) * 128, smem);
}

// ---------------------------------------------------------------------------
// Deformable sampling v4: one warp per (b, q, HEAD-PAIR).
// Lane = head_sel(bit4) * 16 + slot(bit3) * 8 + c4(bits0-2):
//   head_sel 0/1 -> head 2h / 2h+1 ; slot = point parity ; c4 = channel quad.
// Phase 1: all 32 lanes compute one point each (16 per head).
// Phase 2: 8 iterations x (2 heads x 2 slots) parallel points, float4 loads
//   (8 contiguous lanes per corner = one 128B L1 wavefront).
// Gather wavefront count per head unchanged vs v3; phase-1/softmax cost and
// warp count halve. Output written directly as split-bf16 rows of g_Aat.
// ---------------------------------------------------------------------------
__global__ __launch_bounds__(256) void msda_sample(
    const float* __restrict__ v, const float* __restrict__ off,
    const float* __restrict__ aw, const float* __restrict__ ref,
    __nv_bfloat16* __restrict__ outs)   // (B*NQ, 512) = [hi|lo]
{
    const int wid  = threadIdx.x >> 5;            // 0..7
    const int lane = threadIdx.x & 31;
    const int bq   = blockIdx.x * 2 + (wid >> 2); // 2 queries per block
    const int hp   = wid & 3;                     // head pair 0..3
    const int b    = bq / NQ;
    const unsigned FULL = 0xffffffffu;

    const int head_sel = lane >> 4;               // 0 or 1
    const int j        = lane & 15;               // point index within head

    // ---- softmax over 16 logits, both heads at once (width-16 lanes) ----
    // aw row: 32 consecutive floats = logits of heads 2hp, 2hp+1
    const float a = aw[((size_t)bq * NHEADS + hp * 2) * 16 + lane];
    float m = a;
#pragma unroll
    for (int o = 8; o; o >>= 1) m = fmaxf(m, __shfl_xor_sync(FULL, m, o));
    const float e = expf(a - m);
    float s = e;
#pragma unroll
    for (int o = 8; o; o >>= 1) s += __shfl_xor_sync(FULL, s, o);
    const float p = e / s;    // prob of this lane's point

    // ---- phase 1: every lane computes its point's base offset + weights ----
    // offsets for this head pair: 64 consecutive floats
    const float* offp = off + (size_t)bq * EMBED + hp * 64;
    const float offv0 = offp[lane];          // head 2hp   : pts 0-15 (x,y)
    const float offv1 = offp[32 + lane];     // head 2hp+1 : pts 0-15 (x,y)
    const float oxA = __shfl_sync(FULL, offv0, 2 * j);
    const float oyA = __shfl_sync(FULL, offv0, 2 * j + 1);
    const float oxB = __shfl_sync(FULL, offv1, 2 * j);
    const float oyB = __shfl_sync(FULL, offv1, 2 * j + 1);
    const float ox = head_sel ? oxB : oxA;
    const float oy = head_sel ? oyB : oyA;

    const float refv = (lane < 8) ? ref[(size_t)bq * 8 + lane] : 0.f;
    const int   l  = (j >> 2) & 3;                // level of this point
    const float rx = __shfl_sync(FULL, refv, 2 * l);
    const float ry = __shfl_sync(FULL, refv, 2 * l + 1);

    const int   Wi  = 64 >> l;
    const float Wf  = (float)Wi;
    const int   cur = (16384 - (16384 >> (2 * l))) / 3;

    const float px = (rx + ox / Wf) * Wf - 0.5f;
    const float py = (ry + oy / Wf) * Wf - 0.5f;
    const float x0f = floorf(px), y0f = floorf(py);
    const float wx = px - x0f,    wy = py - y0f;
    const int x0 = (int)x0f, y0 = (int)y0f;

    const bool vx0 = (x0 >= 0)  & (x0 < Wi);
    const bool vx1 = (x0 >= -1) & (x0 < Wi - 1);
    const bool vy0 = (y0 >= 0)  & (y0 < Wi);
    const bool vy1 = (y0 >= -1) & (y0 < Wi - 1);
    const float u = 1.f - wx, t = 1.f - wy;

    float c00 = (vx0 && vy0) ? p * u  * t  : 0.f;
    float c10 = (vx1 && vy0) ? p * wx * t  : 0.f;
    float c01 = (vx0 && vy1) ? p * u  * wy : 0.f;
    float c11 = (vx1 && vy1) ? p * wx * wy : 0.f;

    int idx = cur + y0 * Wi + x0;
    idx = min(max(idx, -65), NV - 1);
    const int o00 = idx << 10;

    // ---- phase 2: 8 iterations; this lane gathers point (it*2 + slot) of
    //      head (2hp + head_sel), channel quad c4 ----
    const int slot = (lane >> 3) & 1;
    const int c4   = lane & 7;
    const int myhead = hp * 2 + head_sel;
    const char* vb = (const char*)(v + (size_t)b * NV * EMBED + myhead * 32 + c4 * 4);
    const int srcbase = head_sel * 16 + slot;     // shfl source lane base

    float a0 = 0.f, a1 = 0.f, a2 = 0.f, a3 = 0.f;
#pragma unroll
    for (int it = 0; it < 8; it++) {
        const int rowB = (64 >> (it >> 1)) << 10;   // level = it>>1 (uniform)
        const int src  = srcbase + it * 2;          // point j = it*2 + slot
        const int   io  = __shfl_sync(FULL, o00, src);
        const float w00 = __shfl_sync(FULL, c00, src);
        const float w10 = __shfl_sync(FULL, c10, src);
        const float w01 = __shfl_sync(FULL, c01, src);
        const float w11 = __shfl_sync(FULL, c11, src);
        const char* ad = vb + io;
        const float4 v00 = *(const float4*)(ad);
        const float4 v10 = *(const float4*)(ad + 1024);
        const float4 v01 = *(const float4*)(ad + rowB);
        const float4 v11 = *(const float4*)(ad + rowB + 1024);
        a0 = fmaf(w00, v00.x, a0); a1 = fmaf(w00, v00.y, a1);
        a2 = fmaf(w00, v00.z, a2); a3 = fmaf(w00, v00.w, a3);
        a0 = fmaf(w10, v10.x, a0); a1 = fmaf(w10, v10.y, a1);
        a2 = fmaf(w10, v10.z, a2); a3 = fmaf(w10, v10.w, a3);
        a0 = fmaf(w01, v01.x, a0); a1 = fmaf(w01, v01.y, a1);
        a2 = fmaf(w01, v01.z, a2); a3 = fmaf(w01, v01.w, a3);
        a0 = fmaf(w11, v11.x, a0); a1 = fmaf(w11, v11.y, a1);
        a2 = fmaf(w11, v11.z, a2); a3 = fmaf(w11, v11.w, a3);
    }
    // combine the two point slots of this head (lane bit 3)
    a0 += __shfl_xor_sync(FULL, a0, 8);  a1 += __shfl_xor_sync(FULL, a1, 8);
    a2 += __shfl_xor_sync(FULL, a2, 8);  a3 += __shfl_xor_sync(FULL, a3, 8);

    // ---- epilogue: split-bf16 write (slot-0 lanes of each head) ----
    if (slot == 0) {
        alignas(8) __nv_bfloat16 h[4], lo[4];
        h[0] = __float2bfloat16(a0); lo[0] = __float2bfloat16(a0 - __bfloat162float(h[0]));
        h[1] = __float2bfloat16(a1); lo[1] = __float2bfloat16(a1 - __bfloat162float(h[1]));
        h[2] = __float2bfloat16(a2); lo[2] = __float2bfloat16(a2 - __bfloat162float(h[2]));
        h[3] = __float2bfloat16(a3); lo[3] = __float2bfloat16(a3 - __bfloat162float(h[3]));
        const size_t base = (size_t)bq * KSPLIT + myhead * 32 + c4 * 4;
        *(uint2*)(outs + base)       = *(uint2*)h;
        *(uint2*)(outs + base + 256) = *(uint2*)lo;
    }
}

// ---------------------------------------------------------------------------
// Launch (4 launches total)
// ---------------------------------------------------------------------------
extern "C" void kernel_launch(void* const* d_in, const int* in_sizes, int n_in,
                              void* d_out, int out_size)
{
    const float* query = (const float*)d_in[0];
    const float* value = (const float*)d_in[1];
    const float* refp  = (const float*)d_in[2];
    const float* Wv    = (const float*)d_in[3];
    const float* bv    = (const float*)d_in[4];
    const float* Wo    = (const float*)d_in[5];
    const float* bo    = (const float*)d_in[6];
    const float* Wa    = (const float*)d_in[7];
    const float* ba    = (const float*)d_in[8];
    const float* Wout  = (const float*)d_in[9];
    const float* bout  = (const float*)d_in[10];
    float* out = (float*)d_out;

    float *pvraw, *poff, *paw;
    __nv_bfloat16 *pAv, *pAq, *pAat, *pBv, *pBo, *pBa, *pBout;
    cudaGetSymbolAddress((void**)&pvraw, g_vbuf);
    cudaGetSymbolAddress((void**)&poff,  g_off);
    cudaGetSymbolAddress((void**)&paw,   g_aw);
    cudaGetSymbolAddress((void**)&pAv,   g_Av);
    cudaGetSymbolAddress((void**)&pAq,   g_Aq);
    cudaGetSymbolAddress((void**)&pAat,  g_Aat);
    cudaGetSymbolAddress((void**)&pBv,   g_Bv);
    cudaGetSymbolAddress((void**)&pBo,   g_Bo);
    cudaGetSymbolAddress((void**)&pBa,   g_Ba);
    cudaGetSymbolAddress((void**)&pBout, g_Bout);
    float* pv = pvraw + VPAD;

    cudaFuncSetAttribute(gemm_fused3, cudaFuncAttributeMaxDynamicSharedMemorySize, GSMEM);
    cudaFuncSetAttribute(gemm_out,    cudaFuncAttributeMaxDynamicSharedMemorySize, GSMEM);

    conv_all<<<11776, 256>>>(value, query, Wv, Wo, Wa, Wout,
                             pAv, pAq, pBv, pBo, pBa, pBout);

    gemm_fused3<<<850, 256, GSMEM>>>(pAv, pAq, pBv, pBo, pBa,
                                     bv, bo, ba, pv, poff, paw);

    msda_sample<<<MROWS / 2, 256>>>(pv, poff, paw, refp, pAat);

    gemm_out<<<340, 256, GSMEM>>>(pAat, pBout, bout, out);
}